// round 17
// baseline (speedup 1.0000x reference)
#include <cuda_runtime.h>
#include <cuda_fp16.h>
#include <cstdint>
#include <math.h>

// Problem constants (fixed by the reference setup)
#define BATCH 64
#define QN    900
#define CN    365
#define MN    (BATCH * QN)          // 57600 rows

// Output layout in d_out (float32, tuple order: scores, boxes_int, keep)
#define OFF_BOX  (MN * CN)          // 21,024,000
#define OFF_KEEP (OFF_BOX + MN * 4) // 21,254,400

#define NVCAP 512                   // max valid entries per image (mean ~247, ~20 sigma)
#define MASKW 8

#define K2N   184                   // fp16 k2-pairs per row (covers k<368)
#define K4N   92                    // fp8 k4-groups per row (covers k<368)
#define BPAD  368                   // padded B row length (16B-aligned rows)

// -------- device scratch --------
__device__ int      g_rows[BATCH * NVCAP];
__device__ int      g_cnt [BATCH];
__device__ __align__(16) unsigned g_Bh2[K2N * BPAD];  // B fp16-hi, k2-pair packed
__device__ __align__(16) unsigned g_B8 [K4N * BPAD];  // e4m3(B), k4 packed
__device__ __align__(16) unsigned g_Br8[K4N * BPAD];  // e5m2(B - fp16(B)), k4 packed

// ---- cp.async helpers ----
__device__ __forceinline__ void cp_async4(unsigned dst, const void* src, int sz) {
    asm volatile("cp.async.ca.shared.global [%0], [%1], 4, %2;\n"
                 :: "r"(dst), "l"(src), "r"(sz));
}
__device__ __forceinline__ void cp_async16s(unsigned dst, const void* src, int sz) {
    asm volatile("cp.async.cg.shared.global [%0], [%1], 16, %2;\n"
                 :: "r"(dst), "l"(src), "r"(sz));
}
#define CP_COMMIT() asm volatile("cp.async.commit_group;\n" ::: "memory")
#define CP_WAIT0()  asm volatile("cp.async.wait_group 0;\n" ::: "memory")

// ---- fp16 / fp8 pack helpers ----
__device__ __forceinline__ unsigned pack_h2(float a, float b) {
    __half2 h = __floats2half2_rn(a, b);          // low half = a
    return *reinterpret_cast<unsigned*>(&h);
}
__device__ __forceinline__ unsigned pack_e4m3x4(float a0, float a1, float a2, float a3) {
    unsigned short lo, hi;
    asm("cvt.rn.satfinite.e4m3x2.f32 %0, %1, %2;" : "=h"(lo) : "f"(a1), "f"(a0));
    asm("cvt.rn.satfinite.e4m3x2.f32 %0, %1, %2;" : "=h"(hi) : "f"(a3), "f"(a2));
    return (unsigned)lo | ((unsigned)hi << 16);
}
__device__ __forceinline__ unsigned pack_e5m2x4(float a0, float a1, float a2, float a3) {
    unsigned short lo, hi;
    asm("cvt.rn.satfinite.e5m2x2.f32 %0, %1, %2;" : "=h"(lo) : "f"(a1), "f"(a0));
    asm("cvt.rn.satfinite.e5m2x2.f32 %0, %1, %2;" : "=h"(hi) : "f"(a3), "f"(a2));
    return (unsigned)lo | ((unsigned)hi << 16);
}

#define MMA_F16(d0,d1,d2,d3, a0,a1,a2,a3, b0,b1)                           \
    asm volatile("mma.sync.aligned.m16n8k16.row.col.f32.f16.f16.f32 "      \
                 "{%0,%1,%2,%3}, {%4,%5,%6,%7}, {%8,%9}, {%0,%1,%2,%3};\n" \
                 : "+f"(d0), "+f"(d1), "+f"(d2), "+f"(d3)                  \
                 : "r"(a0), "r"(a1), "r"(a2), "r"(a3), "r"(b0), "r"(b1))
#define MMA_FP8_HL(d0,d1,d2,d3, a0,a1,a2,a3, b0,b1)                        \
    asm volatile("mma.sync.aligned.m16n8k32.row.col.f32.e4m3.e5m2.f32 "    \
                 "{%0,%1,%2,%3}, {%4,%5,%6,%7}, {%8,%9}, {%0,%1,%2,%3};\n" \
                 : "+f"(d0), "+f"(d1), "+f"(d2), "+f"(d3)                  \
                 : "r"(a0), "r"(a1), "r"(a2), "r"(a3), "r"(b0), "r"(b1))
#define MMA_FP8_LH(d0,d1,d2,d3, a0,a1,a2,a3, b0,b1)                        \
    asm volatile("mma.sync.aligned.m16n8k32.row.col.f32.e5m2.e4m3.f32 "    \
                 "{%0,%1,%2,%3}, {%4,%5,%6,%7}, {%8,%9}, {%0,%1,%2,%3};\n" \
                 : "+f"(d0), "+f"(d1), "+f"(d2), "+f"(d3)                  \
                 : "r"(a0), "r"(a1), "r"(a2), "r"(a3), "r"(b0), "r"(b1))

// ============================================================
// Kernel 1 (round-10 structure):
//   [0,64): per-image prep + NMS
//   [64, 64+1024): zero the scores region
//   [64+1024, ...): B operand prep (fp16 pairs + fp8 k4 packs, 368-padded)
// ============================================================
#define NMS_THREADS 512
#define ZBLK 1024
#define CBLK 67                         // ceil(92*368 / 512)
// dynamic smem layout (bytes)
#define SB_BOXO  0
#define SB_SCORE 14400
#define SB_LIST  18000
#define SB_KEY   20048
#define SB_BOXS  22096
#define SB_MASK  30288
#define SB_KP    63056
#define SB_CNT   63568
#define SB_TOTAL 63576

__global__ void __launch_bounds__(NMS_THREADS, 1)
nms_zero_kernel(const float* __restrict__ human,
                const float* __restrict__ bbox,
                const float* __restrict__ Aaug,
                float* __restrict__ out)
{
    int t = threadIdx.x;

    // ---------- B prep blocks ----------
    if (blockIdx.x >= BATCH + ZBLK) {
        int i = (blockIdx.x - (BATCH + ZBLK)) * NMS_THREADS + t;
        if (i < K4N * BPAD) {
            int g = i / BPAD, n = i - g * BPAD;
            float b[4], rl[4];
#pragma unroll
            for (int j = 0; j < 4; j++) {
                int k = 4 * g + j;
                b[j] = (k < CN && n < CN) ? Aaug[k * CN + n] : 0.0f;
                __half h = __float2half_rn(b[j]);
                rl[j] = b[j] - __half2float(h);
            }
            g_Bh2[(2 * g)     * BPAD + n] = pack_h2(b[0], b[1]);
            g_Bh2[(2 * g + 1) * BPAD + n] = pack_h2(b[2], b[3]);
            g_B8 [g * BPAD + n] = pack_e4m3x4(b[0], b[1], b[2], b[3]);
            g_Br8[g * BPAD + n] = pack_e5m2x4(rl[0], rl[1], rl[2], rl[3]);
        }
        return;
    }

    // ---------- zero-fill blocks ----------
    if (blockIdx.x >= BATCH) {
        const size_t total4 = (size_t)MN * CN / 4;
        float4 z = make_float4(0.f, 0.f, 0.f, 0.f);
        size_t stride = (size_t)ZBLK * NMS_THREADS;
        for (size_t p = (size_t)(blockIdx.x - BATCH) * NMS_THREADS + t;
             p < total4; p += stride)
            reinterpret_cast<float4*>(out)[p] = z;
        return;
    }

    // ---------- NMS blocks ----------
    extern __shared__ unsigned char sm[];
    float4*             sboxO  = (float4*)(sm + SB_BOXO);
    float*              sscore = (float*) (sm + SB_SCORE);
    int*                slist  = (int*)   (sm + SB_LIST);
    float*              skey   = (float*) (sm + SB_KEY);
    float4*             sboxS  = (float4*)(sm + SB_BOXS);
    unsigned long long* smask  = (unsigned long long*)(sm + SB_MASK);
    unsigned char*      skp    = sm + SB_KP;
    int*                scnt   = (int*)   (sm + SB_CNT);

    int b = blockIdx.x;
    int base = b * QN;
    float4* outBox4 = reinterpret_cast<float4*>(out + OFF_BOX);

    if (t == 0) *scnt = 0;
    for (int q = t; q < QN; q += NMS_THREADS) {
        float2 h = reinterpret_cast<const float2*>(human)[base + q];
        float d = h.x - h.y;
        float p = 1.0f / (1.0f + expf(-fabsf(d)));
        bool valid = (d >= 0.0f) && (p >= 0.7f);

        float4 bb = reinterpret_cast<const float4*>(bbox)[base + q];
        float x1 = (bb.x - 0.5f * bb.z) * 1333.0f;
        float y1 = (bb.y - 0.5f * bb.w) * 800.0f;
        float x2 = (bb.x + 0.5f * bb.z) * 1333.0f;
        float y2 = (bb.y + 0.5f * bb.w) * 800.0f;
        sboxO[q]  = make_float4(x1, y1, x2, y2);
        sscore[q] = valid ? p : -INFINITY;

        outBox4[base + q] = make_float4((float)(int)x1, (float)(int)y1,
                                        (float)(int)x2, (float)(int)y2);
        out[OFF_KEEP + base + q] = 0.0f;
    }
    __syncthreads();

    for (int q = t; q < QN; q += NMS_THREADS) {
        if (sscore[q] != -INFINITY) {
            int pos = atomicAdd(scnt, 1);
            if (pos < NVCAP) slist[pos] = q;
        }
    }
    __syncthreads();
    int nv = min(*scnt, NVCAP);

    skey[t] = (t < nv) ? sscore[slist[t]] : -INFINITY;
    if (t >= nv) slist[t] = 0;
    skp[t] = 0;
    __syncthreads();
    for (int k = 2; k <= NVCAP; k <<= 1) {
        for (int j = k >> 1; j > 0; j >>= 1) {
            int ixj = t ^ j;
            if (ixj > t) {
                bool desc = ((t & k) == 0);
                float k1 = skey[t], k2 = skey[ixj];
                if (desc ? (k1 < k2) : (k1 > k2)) {
                    skey[t] = k2; skey[ixj] = k1;
                    int tmp = slist[t]; slist[t] = slist[ixj]; slist[ixj] = tmp;
                }
            }
            __syncthreads();
        }
    }

    if (t < nv) sboxS[t] = sboxO[slist[t]];
    __syncthreads();

    int nw = (nv + 63) >> 6;
    for (int flat = t; flat < nv * nw; flat += NMS_THREADS) {
        int i = flat / nw;
        int w = flat - i * nw;
        int jbase = w << 6;
        unsigned long long bits = 0ull;
        int jstart = max(jbase, i + 1);
        int jend   = min(jbase + 63, nv - 1);
        if (jstart <= jend) {
            float4 bi = sboxS[i];
            float areai = (bi.z - bi.x) * (bi.w - bi.y);
            for (int j = jstart; j <= jend; j++) {
                float4 bj = sboxS[j];
                float xx1 = fmaxf(bi.x, bj.x);
                float yy1 = fmaxf(bi.y, bj.y);
                float xx2 = fminf(bi.z, bj.z);
                float yy2 = fminf(bi.w, bj.w);
                float ww = fmaxf(xx2 - xx1, 0.0f);
                float hh = fmaxf(yy2 - yy1, 0.0f);
                float inter = ww * hh;
                float areaj = (bj.z - bj.x) * (bj.w - bj.y);
                float uni = fmaxf(areai + areaj - inter, 1e-9f);
                if (inter > 0.5f * uni) bits |= (1ull << (j - jbase));
            }
        }
        smask[i * MASKW + w] = bits;
    }
    __syncthreads();

    if (t < 32) {
        unsigned long long remv = 0ull;
        for (int i = 0; i < nv; i++) {
            unsigned long long word = __shfl_sync(0xffffffffu, remv, i >> 6);
            bool sup = (word >> (i & 63)) & 1ull;
            if (!sup) {
                if (t == 0) skp[i] = 1;
                if (t < nw) remv |= smask[i * MASKW + t];
            }
        }
    }
    __syncthreads();

    if (t == 0) *scnt = 0;
    __syncthreads();
    if (t < nv && skp[t]) {
        out[OFF_KEEP + base + slist[t]] = 1.0f;
        int pos = atomicAdd(scnt, 1);
        g_rows[b * NVCAP + pos] = base + slist[t];
    }
    __syncthreads();
    if (t == 0) g_cnt[b] = *scnt;
}

// ============================================================
// Kernel 2: prob = logits[kept rows] @ Aaug.
// Per k32: 2x fp16 m16n8k16 (hh) + 2x fp8 m16n8k32 cross terms.
// 256 threads, warp grid 2x4, warp tile 64x32. grid (3,4,64).
// ============================================================
#define GBM 128
#define GBK 32
#define NT  12                      // 12*32 = 384 >= 365 (zero-padded)
// dynamic smem offsets (bytes)
#define GO_RAW  0                   // float [2][128][36] : 36864
#define GO_AH2  36864               // u32 [128][20]      : 10240
#define GO_AH8  47104               // u32 [128][12]      : 6144
#define GO_AL8  53248               // u32 [128][12]      : 6144
#define GO_BH2  59392               // u32 [2][16][136]   : 17408
#define GO_BH8  76800               // u32 [2][8][136]    : 8704
#define GO_BL8  85504               // u32 [2][8][136]    : 8704
#define GO_ROWS 94208               // int [128]          : 512
#define GO_TOTAL 94720

__global__ void __launch_bounds__(256, 2)
gemm_epi_kernel(const float* __restrict__ A,   // [MN, 365]
                float* __restrict__ out)
{
    extern __shared__ unsigned char sm[];
    float*    rawA  = (float*)   (sm + GO_RAW);
    unsigned* Ah2   = (unsigned*)(sm + GO_AH2);
    unsigned* Ah8   = (unsigned*)(sm + GO_AH8);
    unsigned* Al8   = (unsigned*)(sm + GO_AL8);
    unsigned* Bh2   = (unsigned*)(sm + GO_BH2);
    unsigned* Bh8   = (unsigned*)(sm + GO_BH8);
    unsigned* Bl8   = (unsigned*)(sm + GO_BL8);
    int*      rows_s = (int*)    (sm + GO_ROWS);

    const int N = CN;
    int bz  = blockIdx.z;
    int cnt = g_cnt[bz];
    int m0  = blockIdx.y * GBM;
    if (m0 >= cnt) return;
    int n0 = blockIdx.x * 128;

    int t    = threadIdx.x;
    int lane = t & 31;
    int gid  = lane >> 2;
    int tig  = lane & 3;
    int warp = t >> 5;
    int wM   = warp >> 2;           // 0..1
    int wN   = warp & 3;            // 0..3

    if (t < GBM) {
        int mi = m0 + t;
        rows_s[t] = g_rows[bz * NVCAP + (mi < cnt ? mi : cnt - 1)];
    }
    __syncthreads();

    // ---- tile loader ----
    auto load_tile = [&](int buf, int it) {
        int k0 = it * GBK;
        // A raw fp32: 128 rows x 32 k, cp4 (row base not 16B-aligned)
#pragma unroll
        for (int u = 0; u < 16; u++) {
            int e = t + u * 256;
            int row = e >> 5, k = e & 31;
            int kk = k0 + k;
            int sz = (kk < CN) ? 4 : 0;
            int kc = (kk < CN) ? kk : (CN - 1);
            unsigned dst = (unsigned)__cvta_generic_to_shared(
                &rawA[(buf * GBM + row) * 36 + k]);
            cp_async4(dst, A + (size_t)rows_s[row] * CN + kc, sz);
        }
        // Bh2: 16 k2-rows x 128 n (cp16, 368-padded rows are 16B aligned)
        int k20 = it * 16;
#pragma unroll
        for (int u = 0; u < 2; u++) {
            int c = t + u * 256;
            int r = c >> 5, nc = c & 31;
            int k2 = k20 + r;
            int nn = n0 + 4 * nc;
            int sz = (k2 < K2N) ? max(0, min(BPAD - nn, 4)) * 4 : 0;
            int k2c = (k2 < K2N) ? k2 : (K2N - 1);
            int nnc = (nn < BPAD) ? nn : (BPAD - 4);
            unsigned dst = (unsigned)__cvta_generic_to_shared(
                &Bh2[(buf * 16 + r) * 136 + nc * 4]);
            cp_async16s(dst, g_Bh2 + (size_t)k2c * BPAD + nnc, sz);
        }
        // B8 / Br8: 8 k4-rows x 128 n each
        int k40 = it * 8;
#pragma unroll
        for (int u = 0; u < 2; u++) {
            int c = t + u * 256;
            int half = c >> 8;                  // 0: hi(e4m3), 1: lo(e5m2)
            int cc = c & 255;
            int r = cc >> 5, nc = cc & 31;
            int g = k40 + r;
            int nn = n0 + 4 * nc;
            int sz = (g < K4N) ? max(0, min(BPAD - nn, 4)) * 4 : 0;
            int gc = (g < K4N) ? g : (K4N - 1);
            int nnc = (nn < BPAD) ? nn : (BPAD - 4);
            unsigned dst = (unsigned)__cvta_generic_to_shared(
                (half ? Bl8 : Bh8) + (buf * 8 + r) * 136 + nc * 4);
            cp_async16s(dst, (half ? g_Br8 : g_B8) + (size_t)gc * BPAD + nnc, sz);
        }
        CP_COMMIT();
    };

    load_tile(0, 0);

    float acc[4][4][4];
#pragma unroll
    for (int i = 0; i < 4; i++)
#pragma unroll
        for (int j = 0; j < 4; j++)
#pragma unroll
            for (int c = 0; c < 4; c++) acc[i][j][c] = 0.0f;

    for (int it = 0; it < NT; it++) {
        int p = it & 1;
        CP_WAIT0();
        __syncthreads();            // raw[p]/B[p] ready; prior MMAs done with conv arrays
        if (it + 1 < NT)
            load_tile(1 - p, it + 1);

        // block-wide A conversion: raw fp32 -> Ah2 (fp16 pairs) + Ah8/Al8 (fp8 k4)
#pragma unroll
        for (int u = 0; u < 4; u++) {
            int idx = t + u * 256;              // 0..1023: 128 rows x 8 k4-groups
            int row = idx >> 3, g = idx & 7;
            float4 v = *reinterpret_cast<float4*>(&rawA[(p * GBM + row) * 36 + 4 * g]);
            __half h0 = __float2half_rn(v.x), h1 = __float2half_rn(v.y);
            __half h2 = __float2half_rn(v.z), h3 = __float2half_rn(v.w);
            float r0 = v.x - __half2float(h0), r1 = v.y - __half2float(h1);
            float r2 = v.z - __half2float(h2), r3 = v.w - __half2float(h3);
            __half2 p0 = __halves2half2(h0, h1), p1 = __halves2half2(h2, h3);
            Ah2[row * 20 + 2 * g]     = *reinterpret_cast<unsigned*>(&p0);
            Ah2[row * 20 + 2 * g + 1] = *reinterpret_cast<unsigned*>(&p1);
            Ah8[row * 12 + g] = pack_e4m3x4(v.x, v.y, v.z, v.w);
            Al8[row * 12 + g] = pack_e5m2x4(r0, r1, r2, r3);
        }
        __syncthreads();

        int nlocs[4];
#pragma unroll
        for (int wn = 0; wn < 4; wn++) nlocs[wn] = wN * 32 + wn * 8 + gid;

        // fp16 hh terms: 2 k16 subchunks
#pragma unroll
        for (int s = 0; s < 2; s++) {
            unsigned bh[4][2];
#pragma unroll
            for (int wn = 0; wn < 4; wn++) {
                bh[wn][0] = Bh2[(p * 16 + s * 8 + tig)     * 136 + nlocs[wn]];
                bh[wn][1] = Bh2[(p * 16 + s * 8 + tig + 4) * 136 + nlocs[wn]];
            }
#pragma unroll
            for (int wm = 0; wm < 4; wm++) {
                int r0 = wM * 64 + wm * 16 + gid;
                int r1 = r0 + 8;
                unsigned a0 = Ah2[r0 * 20 + s * 8 + tig];
                unsigned a1 = Ah2[r1 * 20 + s * 8 + tig];
                unsigned a2 = Ah2[r0 * 20 + s * 8 + tig + 4];
                unsigned a3 = Ah2[r1 * 20 + s * 8 + tig + 4];
#pragma unroll
                for (int wn = 0; wn < 4; wn++)
                    MMA_F16(acc[wm][wn][0], acc[wm][wn][1], acc[wm][wn][2], acc[wm][wn][3],
                            a0, a1, a2, a3, bh[wn][0], bh[wn][1]);
            }
        }

        // fp8 cross terms: k32
        unsigned b8h[4][2], b8l[4][2];
#pragma unroll
        for (int wn = 0; wn < 4; wn++) {
            b8h[wn][0] = Bh8[(p * 8 + tig)     * 136 + nlocs[wn]];
            b8h[wn][1] = Bh8[(p * 8 + tig + 4) * 136 + nlocs[wn]];
            b8l[wn][0] = Bl8[(p * 8 + tig)     * 136 + nlocs[wn]];
            b8l[wn][1] = Bl8[(p * 8 + tig + 4) * 136 + nlocs[wn]];
        }
#pragma unroll
        for (int wm = 0; wm < 4; wm++) {
            int r0 = wM * 64 + wm * 16 + gid;
            int r1 = r0 + 8;
            unsigned ah0 = Ah8[r0 * 12 + tig],     ah1 = Ah8[r1 * 12 + tig];
            unsigned ah2v = Ah8[r0 * 12 + tig + 4], ah3 = Ah8[r1 * 12 + tig + 4];
            unsigned al0 = Al8[r0 * 12 + tig],     al1 = Al8[r1 * 12 + tig];
            unsigned al2 = Al8[r0 * 12 + tig + 4], al3 = Al8[r1 * 12 + tig + 4];
#pragma unroll
            for (int wn = 0; wn < 4; wn++) {
                MMA_FP8_HL(acc[wm][wn][0], acc[wm][wn][1], acc[wm][wn][2], acc[wm][wn][3],
                           ah0, ah1, ah2v, ah3, b8l[wn][0], b8l[wn][1]);
                MMA_FP8_LH(acc[wm][wn][0], acc[wm][wn][1], acc[wm][wn][2], acc[wm][wn][3],
                           al0, al1, al2, al3, b8h[wn][0], b8h[wn][1]);
            }
        }
    }

    // fused epilogue
#pragma unroll
    for (int wm = 0; wm < 4; wm++) {
#pragma unroll
        for (int half = 0; half < 2; half++) {
            int lm = wM * 64 + wm * 16 + gid + half * 8;
            int mi = m0 + lm;
            if (mi < cnt) {
                size_t rowoff = (size_t)rows_s[lm] * N;
#pragma unroll
                for (int wn = 0; wn < 4; wn++) {
                    int n = n0 + wN * 32 + wn * 8 + 2 * tig;
                    float v0 = acc[wm][wn][half * 2 + 0];
                    float v1 = acc[wm][wn][half * 2 + 1];
                    if (n < N)
                        out[rowoff + n]     = (v0 >= 0.25f) ? (v0 + 1.0f) * 0.5f : 0.0f;
                    if (n + 1 < N)
                        out[rowoff + n + 1] = (v1 >= 0.25f) ? (v1 + 1.0f) * 0.5f : 0.0f;
                }
            }
        }
    }
}

// ============================================================
extern "C" void kernel_launch(void* const* d_in, const int* in_sizes, int n_in,
                              void* d_out, int out_size)
{
    const float* human  = (const float*)d_in[0]; // [B,Q,2]
    const float* logits = (const float*)d_in[1]; // [B,Q,C]
    const float* bbox   = (const float*)d_in[2]; // [B,Q,4]
    const float* Aaug   = (const float*)d_in[3]; // [C,C]
    float* out = (float*)d_out;

    cudaFuncSetAttribute(nms_zero_kernel,
                         cudaFuncAttributeMaxDynamicSharedMemorySize, SB_TOTAL);
    cudaFuncSetAttribute(gemm_epi_kernel,
                         cudaFuncAttributeMaxDynamicSharedMemorySize, GO_TOTAL);

    // [0,64): prep+NMS; [64,1088): zero scores; [1088,1155): B prep
    nms_zero_kernel<<<BATCH + ZBLK + CBLK, NMS_THREADS, SB_TOTAL>>>(human, bbox, Aaug, out);

    gemm_epi_kernel<<<dim3(3, NVCAP / GBM, BATCH), 256, GO_TOTAL>>>(logits, out);
}